// round 1
// baseline (speedup 1.0000x reference)
#include <cuda_runtime.h>

#define NB     16
#define NP     65536
#define RAD_N  5
#define AZI_N  30
#define ELE_N  15
#define NSLOT  (NB * RAD_N * AZI_N * (ELE_N - 1))   // 33600 float2 pair-slots
#define NOUT   (NB * RAD_N * AZI_N * ELE_N)         // 36000 output bins

// Overlapping pair-slot histogram: slot[b][r][a][k] (k=0..13) holds
// (.x = contribution to ele bin k, .y = contribution to ele bin k+1).
// Final: out[e] = slot[e].x + slot[e-1].y
__device__ float2 g_slots[NSLOT];

__device__ __forceinline__ void red_add2(float2* a, float x, float y) {
    asm volatile("red.global.add.v2.f32 [%0], {%1, %2};"
                 :: "l"(a), "f"(x), "f"(y) : "memory");
}

__global__ void zero_kernel() {
    int i = blockIdx.x * blockDim.x + threadIdx.x;
    if (i < NSLOT) g_slots[i] = make_float2(0.f, 0.f);
}

__global__ void __launch_bounds__(256) vox_kernel(const float* __restrict__ pts) {
    int idx = blockIdx.x * blockDim.x + threadIdx.x;   // exact multiple, no guard
    float x = __ldg(pts + 3 * idx);
    float y = __ldg(pts + 3 * idx + 1);
    float z = __ldg(pts + 3 * idx + 2);

    float r = sqrtf(x * x + y * y + z * z);
    if (r > 2.0f) return;   // wr culled -> all 8 weights zero (reference: r > DES_R)

    int b = idx >> 16;      // NP = 65536

    float azi = atan2f(y, x);
    if (azi < 0.f) azi += 6.28318530717958647692f;
    float ce  = fminf(fmaxf(z / fmaxf(r, 1e-12f), -1.f), 1.f);
    float ele = acosf(ce);

    // ---- radial pair: tr=0.4, centers (j+0.5)*tr ----
    // v = r/tr - 0.5; interior: bins (j, j+1), w = (1-f, f)
    // low  (r < sr):  bins (0,1), w = (1, 0)           [ref's half-bin clamp]
    // high (r >= 1.8): bins (3,4), w = (0, 1-(v-4))    [ref zeroes only 2nd bin]
    float vr = r * 2.5f - 0.5f;
    int jr; float wr0, wr1;
    if (vr < 0.f)        { jr = 0; wr0 = 1.f; wr1 = 0.f; }
    else if (vr >= 4.f)  { jr = 3; wr0 = 0.f; wr1 = 5.f - vr; }
    else { jr = (int)vr; float f = vr - (float)jr; wr0 = 1.f - f; wr1 = f; }

    // ---- azimuth pair: circular, ta = 2pi/30 ----
    float va = azi * (float)(AZI_N / 6.283185307179586) - 0.5f;
    float fj = floorf(va);
    int   j  = (int)fj;                 // in [-1, 29]
    float fa = va - fj;
    int ja0 = (j < 0) ? (AZI_N - 1) : j;
    int ja1 = (j >= AZI_N - 1) ? 0 : (j + 1);
    float wa0 = 1.f - fa, wa1 = fa;

    // ---- elevation pair: te = pi/15, both-end half-bin clamps ----
    float ve = ele * (float)(ELE_N / 3.141592653589793) - 0.5f;
    int ke; float we0, we1;
    if (ve < 0.f)         { ke = 0;  we0 = 1.f; we1 = 0.f; }
    else if (ve >= 14.f)  { ke = 13; we0 = 0.f; we1 = 1.f; }
    else { ke = (int)ve; float f = ve - (float)ke; we0 = 1.f - f; we1 = f; }

    int base = (b * RAD_N + jr) * AZI_N;
    float2* s00 = &g_slots[(base + ja0)         * (ELE_N - 1) + ke];
    float2* s01 = &g_slots[(base + ja1)         * (ELE_N - 1) + ke];
    float2* s10 = &g_slots[(base + AZI_N + ja0) * (ELE_N - 1) + ke];  // jr+1 row
    float2* s11 = &g_slots[(base + AZI_N + ja1) * (ELE_N - 1) + ke];

    float w00 = wr0 * wa0, w01 = wr0 * wa1;
    float w10 = wr1 * wa0, w11 = wr1 * wa1;

    red_add2(s00, w00 * we0, w00 * we1);
    red_add2(s01, w01 * we0, w01 * we1);
    red_add2(s10, w10 * we0, w10 * we1);
    red_add2(s11, w11 * we0, w11 * we1);
}

__global__ void reduce_kernel(float* __restrict__ out) {
    int i = blockIdx.x * blockDim.x + threadIdx.x;
    if (i >= NOUT) return;
    int e  = i % ELE_N;
    int ra = i / ELE_N;
    const float2* s = &g_slots[ra * (ELE_N - 1)];
    float v = 0.f;
    if (e < ELE_N - 1) v += s[e].x;
    if (e > 0)         v += s[e - 1].y;
    out[i] = v;
}

extern "C" void kernel_launch(void* const* d_in, const int* in_sizes, int n_in,
                              void* d_out, int out_size) {
    const float* pts = (const float*)d_in[0];
    float* out = (float*)d_out;

    zero_kernel<<<(NSLOT + 255) / 256, 256>>>();
    vox_kernel<<<(NB * NP) / 256, 256>>>(pts);
    reduce_kernel<<<(NOUT + 255) / 256, 256>>>(out);
}

// round 3
// speedup vs baseline: 2.3717x; 2.3717x over previous
#include <cuda_runtime.h>

#define NB     16
#define NP     65536
#define RAD_N  5
#define AZI_N  30
#define ELE_N  15
#define KSL    (ELE_N - 1)                         // 14 ele pair-slots
#define NSLOT  (NB * RAD_N * AZI_N * KSL)          // 33600 float4 2x2-slots
#define NOUT   (NB * RAD_N * AZI_N * ELE_N)        // 36000 output bins

// 2x2 pair-slot histogram: slot[b][r][a][k] (a=0..29 circular, k=0..13) holds
// contributions to the 4 bins (a,k),(a,k+1),(a+1%30,k),(a+1%30,k+1)
// in components (.x, .y, .z, .w) respectively.
__device__ float4 g_slots[NSLOT];

__device__ __forceinline__ void red_add4(float4* a, float x, float y, float z, float w) {
    asm volatile("red.global.add.v4.f32 [%0], {%1, %2, %3, %4};"
                 :: "l"(a), "f"(x), "f"(y), "f"(z), "f"(w) : "memory");
}

__global__ void zero_kernel() {
    int i = blockIdx.x * blockDim.x + threadIdx.x;
    if (i < NSLOT) g_slots[i] = make_float4(0.f, 0.f, 0.f, 0.f);
}

__global__ void __launch_bounds__(256) vox_kernel(const float* __restrict__ pts) {
    int idx = blockIdx.x * blockDim.x + threadIdx.x;   // exact multiple, no guard
    float x = __ldg(pts + 3 * idx);
    float y = __ldg(pts + 3 * idx + 1);
    float z = __ldg(pts + 3 * idx + 2);

    float r = sqrtf(x * x + y * y + z * z);
    if (r > 2.0f) return;   // reference culls r > DES_R (all weights zero)

    int b = idx >> 16;      // NP = 65536

    float azi = atan2f(y, x);
    if (azi < 0.f) azi += 6.28318530717958647692f;
    float ce  = fminf(fmaxf(z / fmaxf(r, 1e-12f), -1.f), 1.f);
    float ele = acosf(ce);

    // ---- radial pair: tr=0.4, closed form of ref's half-bin boundary clamps ----
    float vr = r * 2.5f - 0.5f;
    int jr; float wr0, wr1;
    if (vr < 0.f)        { jr = 0; wr0 = 1.f; wr1 = 0.f; }
    else if (vr >= 4.f)  { jr = 3; wr0 = 0.f; wr1 = 5.f - vr; }
    else { jr = (int)vr; float f = vr - (float)jr; wr0 = 1.f - f; wr1 = f; }

    // ---- azimuth pair: circular; slot sa covers bins (sa, sa+1 mod 30) ----
    float va = azi * (float)(AZI_N / 6.283185307179586) - 0.5f;
    float fj = floorf(va);
    int   j  = (int)fj;                 // in [-1, 29]
    float fa = va - fj;
    int sa = (j < 0) ? (AZI_N - 1) : j;
    float wa0 = 1.f - fa, wa1 = fa;

    // ---- elevation pair: te = pi/15, both-end half-bin clamps ----
    float ve = ele * (float)(ELE_N / 3.141592653589793) - 0.5f;
    int ke; float we0, we1;
    if (ve < 0.f)         { ke = 0;  we0 = 1.f; we1 = 0.f; }
    else if (ve >= 14.f)  { ke = 13; we0 = 0.f; we1 = 1.f; }
    else { ke = (int)ve; float f = ve - (float)ke; we0 = 1.f - f; we1 = f; }

    // 2x2 (azi x ele) weight patch
    float p00 = wa0 * we0, p01 = wa0 * we1;
    float p10 = wa1 * we0, p11 = wa1 * we1;

    int s0 = ((b * RAD_N + jr) * AZI_N + sa) * KSL + ke;
    if (wr0 != 0.f)
        red_add4(&g_slots[s0], wr0 * p00, wr0 * p01, wr0 * p10, wr0 * p11);
    if (wr1 != 0.f)
        red_add4(&g_slots[s0 + AZI_N * KSL], wr1 * p00, wr1 * p01, wr1 * p10, wr1 * p11);
}

__global__ void reduce_kernel(float* __restrict__ out) {
    int i = blockIdx.x * blockDim.x + threadIdx.x;
    if (i >= NOUT) return;
    int e   = i % ELE_N;
    int ra  = i / ELE_N;          // (b*5 + r)*30 + a
    int a   = ra % AZI_N;
    int rb  = ra / AZI_N;         // b*5 + r
    int am1 = (a == 0) ? (AZI_N - 1) : (a - 1);

    const float4* S = g_slots + rb * AZI_N * KSL;
    float v = 0.f;
    if (e < KSL) {                               // k = e components
        v += S[a   * KSL + e].x;
        v += S[am1 * KSL + e].z;
    }
    if (e > 0) {                                 // k = e-1 components
        v += S[a   * KSL + e - 1].y;
        v += S[am1 * KSL + e - 1].w;
    }
    out[i] = v;
}

extern "C" void kernel_launch(void* const* d_in, const int* in_sizes, int n_in,
                              void* d_out, int out_size) {
    const float* pts = (const float*)d_in[0];
    float* out = (float*)d_out;

    zero_kernel<<<(NSLOT + 255) / 256, 256>>>();
    vox_kernel<<<(NB * NP) / 256, 256>>>(pts);
    reduce_kernel<<<(NOUT + 255) / 256, 256>>>(out);
}